// round 17
// baseline (speedup 1.0000x reference)
#include <cuda_runtime.h>
#include <cuda_fp16.h>
#include <cstdint>

// ---------------------------------------------------------------- shapes
#define BB    8
#define CIN   16
#define FD    1024
#define TD    512
#define DD    1024
#define NTOK  512
#define LAY   4
#define MROWS (TD*BB)                 // 4096
#define LOGITS_ELEMS (BB*TD*NTOK)     // 2097152
#define KTOT  DD                      // 1024
#define NSRU  (3*DD)                  // 3072
#define WELEMS ((size_t)(LAY*NSRU + NTOK) * KTOT)

// ---------------------------------------------------------------- scratch
__device__ __half g_Xhi[(size_t)MROWS * DD];
__device__ __half g_Xlo[(size_t)MROWS * DD];
__device__ float  g_U  [(size_t)MROWS * NSRU];
__device__ __half g_Wh [WELEMS];
__device__ unsigned g_prog[32];    // GEMM col-tiles done per row-block (cumulative)
__device__ unsigned g_sprog[32];   // sru units done per row-block (cumulative)
__device__ unsigned g_task;        // work-queue head

// ---------------------------------------------------------------- helpers
__device__ __forceinline__ uint32_t s2u(const void* p) {
    uint32_t a;
    asm("{ .reg .u64 t; cvta.to.shared.u64 t, %1; cvt.u32.u64 %0, t; }"
        : "=r"(a) : "l"(p));
    return a;
}
__device__ __forceinline__ void cpasync16(uint32_t dst, const void* src) {
    asm volatile("cp.async.cg.shared.global [%0], [%1], 16;"
                 :: "r"(dst), "l"(src) : "memory");
}
__device__ __forceinline__ void cpasync4(uint32_t dst, const void* src) {
    asm volatile("cp.async.ca.shared.global [%0], [%1], 4;"
                 :: "r"(dst), "l"(src) : "memory");
}
__device__ __forceinline__ void cp_commit() {
    asm volatile("cp.async.commit_group;" ::: "memory");
}
template <int N>
__device__ __forceinline__ void cp_wait() {
    asm volatile("cp.async.wait_group %0;" :: "n"(N) : "memory");
}
__device__ __forceinline__ void barsync(int id, int cnt) {
    asm volatile("bar.sync %0, %1;" :: "r"(id), "r"(cnt) : "memory");
}
__device__ __forceinline__ void ldm_x4(uint32_t a[4], uint32_t addr) {
    asm volatile("ldmatrix.sync.aligned.m8n8.x4.shared.b16 {%0,%1,%2,%3}, [%4];"
                 : "=r"(a[0]), "=r"(a[1]), "=r"(a[2]), "=r"(a[3]) : "r"(addr));
}
__device__ __forceinline__ void ldm_x4t(uint32_t b[4], uint32_t addr) {
    asm volatile("ldmatrix.sync.aligned.m8n8.x4.trans.shared.b16 {%0,%1,%2,%3}, [%4];"
                 : "=r"(b[0]), "=r"(b[1]), "=r"(b[2]), "=r"(b[3]) : "r"(addr));
}
__device__ __forceinline__ void mma_f16(float c[4], const uint32_t a[4],
                                        const uint32_t b[2]) {
    asm volatile(
        "mma.sync.aligned.m16n8k16.row.col.f32.f16.f16.f32 "
        "{%0,%1,%2,%3}, {%4,%5,%6,%7}, {%8,%9}, {%0,%1,%2,%3};"
        : "+f"(c[0]), "+f"(c[1]), "+f"(c[2]), "+f"(c[3])
        : "r"(a[0]), "r"(a[1]), "r"(a[2]), "r"(a[3]), "r"(b[0]), "r"(b[1]));
}
__device__ __forceinline__ float ex2f(float x) {
    float r;
    asm("ex2.approx.f32 %0, %1;" : "=f"(r) : "f"(x));
    return r;
}
__device__ __forceinline__ float rcpf(float x) {
    float r;
    asm("rcp.approx.f32 %0, %1;" : "=f"(r) : "f"(x));
    return r;
}
__device__ __forceinline__ void f16split(float x, __half& hi, __half& lo) {
    hi = __float2half_rn(x);
    lo = __float2half_rn(x - __half2float(hi));
}
__device__ __forceinline__ unsigned ldcg_u32(const unsigned* p) {
    unsigned v;
    asm volatile("ld.global.cg.u32 %0, [%1];" : "=r"(v) : "l"(p));
    return v;
}

// smem per stage (fp16, BK=64): A 128x(64+8)h = 18432B, B 64x(128+8)h = 17408B.
#define BK      64
#define A_PADB  144
#define B_PADB  272
#define BOFF    18432
#define STAGE_B 35840
#define NSTAGES 3
#define SMEM_GEMM (NSTAGES * STAGE_B)   // 107520
#define NKITER (KTOT / BK)              // 16

// sru constants
#define CHUNK 8
#define RING  32
#define NCH   (TD / CHUNK)   // 64
#define SRU_UNIT_SMEM 32768  // XT/FP/RP [32][64]f32 + XH/XL [32][32]u32

// task queue: per layer 768 GEMM + 64 sru (2 units each); then 128 FC tiles
#define TASKS_PER_LAYER 832
#define NTASKS (LAY * TASKS_PER_LAYER + 128)   // 3456
#define MEGA_GRID 296

// ---------------------------------------------------------------- GEMM load
__device__ __forceinline__ void load_stage(uint32_t st_base,
                                           const __half* __restrict__ Ah,
                                           const __half* __restrict__ Wh,
                                           int rowBase, int colBase, int kt,
                                           int Nglob, int tid) {
    #pragma unroll
    for (int i = 0; i < 4; ++i) {
        const int q = tid + i * 256;
        const int ar = q >> 3, ac = q & 7;
        cpasync16(st_base + ar * A_PADB + ac * 16,
                  Ah + (size_t)(rowBase + ar) * KTOT + kt + ac * 8);
        const int br = q >> 4, bc = q & 15;
        cpasync16(st_base + BOFF + br * B_PADB + bc * 16,
                  Wh + (size_t)(kt + br) * Nglob + colBase + bc * 8);
    }
    cp_commit();
}

// ---------------------------------------------------------------- GEMM tile task
__device__ void gemm_tile(const __half* __restrict__ Ah,
                          const __half* __restrict__ Wg,
                          float* __restrict__ Cout,
                          const float* __restrict__ bias,
                          int Nglob, int rowBase, int colBase,
                          bool fcmode, char* smem_raw, unsigned sgate) {
    const uint32_t sb = s2u(smem_raw);
    const int tid = threadIdx.x;

    if (sgate) {
        if (tid == 0) {
            const unsigned* cp = &g_sprog[rowBase >> 7];
            while (ldcg_u32(cp) < sgate) __nanosleep(64);
        }
        __syncthreads();
        __threadfence();
    }

    const int wid = tid >> 5, lane = tid & 31;
    const int wm = wid & 3, wn = wid >> 2;

    float acc[2][8][4];
    #pragma unroll
    for (int i = 0; i < 2; ++i)
        #pragma unroll
        for (int j = 0; j < 8; ++j)
            #pragma unroll
            for (int k = 0; k < 4; ++k) acc[i][j][k] = 0.0f;

    load_stage(sb,           Ah, Wg, rowBase, colBase, 0,  Nglob, tid);
    load_stage(sb + STAGE_B, Ah, Wg, rowBase, colBase, BK, Nglob, tid);

    const int lr  = lane & 15;
    const int lc  = lane >> 4;
    const int bng = lane >> 4;

    int st = 0;
    for (int k = 0; k < NKITER; ++k) {
        if (k + 2 <= NKITER) cp_wait<1>(); else cp_wait<0>();
        __syncthreads();
        if (k + 2 < NKITER)
            load_stage(sb + ((st + 2) % 3) * STAGE_B, Ah, Wg,
                       rowBase, colBase, (k + 2) * BK, Nglob, tid);

        const uint32_t abase = sb + st * STAGE_B;
        const uint32_t bbase = abase + BOFF;

        #pragma unroll
        for (int kk = 0; kk < 4; ++kk) {
            const int arow0 = wm * 32 + lr;
            const int acolB = (kk * 16 + lc * 8) * 2;
            uint32_t a0[2][4], bfr[4][4];
            #pragma unroll
            for (int mt = 0; mt < 2; ++mt)
                ldm_x4(a0[mt], abase + (arow0 + mt * 16) * A_PADB + acolB);
            const uint32_t brow = bbase + (kk * 16 + lr) * B_PADB;
            #pragma unroll
            for (int np = 0; np < 4; ++np)
                ldm_x4t(bfr[np], brow + (wn * 64 + np * 16 + bng * 8) * 2);
            #pragma unroll
            for (int mt = 0; mt < 2; ++mt)
                #pragma unroll
                for (int np = 0; np < 4; ++np) {
                    mma_f16(acc[mt][2 * np + 0], a0[mt], &bfr[np][0]);
                    mma_f16(acc[mt][2 * np + 1], a0[mt], &bfr[np][2]);
                }
        }
        st = (st + 1) % 3;
    }

    const int rq = lane >> 2;
    const int cq = (lane & 3) * 2;
    #pragma unroll
    for (int mt = 0; mt < 2; ++mt) {
        #pragma unroll
        for (int half = 0; half < 2; ++half) {
            const int m = rowBase + wm * 32 + mt * 16 + half * 8 + rq;
            const int orow = fcmode ? ((m & (BB - 1)) * TD + (m >> 3)) : m;
            float* crow = Cout + (size_t)orow * Nglob + colBase + wn * 64;
            #pragma unroll
            for (int nt = 0; nt < 8; ++nt) {
                float2 vv;
                vv.x = acc[mt][nt][half * 2 + 0];
                vv.y = acc[mt][nt][half * 2 + 1];
                if (fcmode) {
                    vv.x += bias[colBase + wn * 64 + nt * 8 + cq + 0];
                    vv.y += bias[colBase + wn * 64 + nt * 8 + cq + 1];
                }
                *(float2*)(crow + nt * 8 + cq) = vv;
            }
        }
    }
    if (!fcmode) {
        __threadfence();
        __syncthreads();
        if (tid == 0) atomicAdd(&g_prog[rowBase >> 7], 1u);
    }
}

// ---------------------------------------------------------------- SRU task
// One 256-thread CTA runs TWO independent sru units (128 threads each).
// Unit layout: threads 0-63 = combined c+r compute (1 chain/thread),
// threads 64-127 = loaders (4 cp.async/thread/step). Per-unit named
// barriers; publish g_sprog per row-block.
__device__ void sru_task2(const float* __restrict__ U,
                          __half* __restrict__ Xhi, __half* __restrict__ Xlo,
                          const float* __restrict__ v, const float* __restrict__ bb,
                          int upair, unsigned ptarget, char* smem_raw) {
    const int tid = threadIdx.x;
    const int side = tid >> 7;          // unit within CTA
    const int ut = tid & 127;
    const int sblk = upair * 2 + side;  // 0..127
    const int dbase = (sblk & 15) * 64;
    const int b = sblk >> 4;
    const int mainbar = 1 + side;       // 1,2 (128 threads)
    const int pubbar  = 3 + side;       // 3,4 (64 compute threads)
    const int gatebar = 5 + side;       // 5,6 (64 loader threads)

    const size_t us = (size_t)BB * 3 * DD;
    const size_t xs = (size_t)BB * DD;
    const float L2E = 1.4426950408889634f;

    char* um = smem_raw + side * SRU_UNIT_SMEM;
    float*    fXT = (float*)um;
    float*    fFP = (float*)(um + 8192);
    float*    fRP = (float*)(um + 16384);
    uint32_t* uXH = (uint32_t*)(um + 24576);
    uint32_t* uXL = (uint32_t*)(um + 28672);

    if (ut >= 64) {
        // ---------------- loaders ----------------
        const int j = ut - 64;          // 0..63
        const float* ub = U + (size_t)b * 3 * DD + dbase;
        const uint32_t aXT = s2u(fXT) + j * 4;
        const uint32_t aFP = s2u(fFP) + j * 4;
        const uint32_t aRP = s2u(fRP) + j * 4;
        const bool isH = (j < 32);
        const int  pj  = isH ? j : (j - 32);
        const __half* xsrc = (isH ? Xhi : Xlo) + (size_t)b * DD + dbase + 2 * pj;
        const uint32_t aXP = (isH ? s2u(uXH) : s2u(uXL)) + pj * 4;

        #define LOADSTEP(t) do { \
            const int s_ = (t) & (RING - 1); \
            cpasync4(aXT + s_ * 256, ub + j + (size_t)(t) * us); \
            cpasync4(aFP + s_ * 256, ub + DD + j + (size_t)(t) * us); \
            cpasync4(aRP + s_ * 256, ub + 2 * DD + j + (size_t)(t) * us); \
            cpasync4(aXP + s_ * 128, xsrc + (size_t)(t) * xs); \
            cp_commit(); \
        } while (0)
        #define GATE(jj) do { \
            if (ut == 64) { \
                const unsigned* cp = &g_prog[(jj) >> 1]; \
                while (ldcg_u32(cp) < ptarget) __nanosleep(64); \
            } \
            barsync(gatebar, 64); \
        } while (0)

        // prologue: chunks 0,1
        for (int ch = 0; ch < 2; ++ch) {
            GATE(ch);
            #pragma unroll 1
            for (int i = 0; i < CHUNK; ++i) LOADSTEP(ch * CHUNK + i);
        }
        cp_wait<CHUNK>();

        for (int k = 0; k < NCH; ++k) {
            barsync(mainbar, 128);
            if (k + 2 < NCH) {
                GATE(k + 2);
                #pragma unroll 1
                for (int i = 0; i < CHUNK; ++i) LOADSTEP((k + 2) * CHUNK + i);
                cp_wait<CHUNK>();
            } else {
                cp_wait<0>();
            }
        }
        #undef GATE
        #undef LOADSTEP
    } else {
        // ---------------- combined c+r compute ----------------
        const int ch = ut;              // chain 0..63
        const int d = dbase + ch;
        const float vf2 = -v[d]      * L2E;
        const float vr2 = -v[DD + d] * L2E;
        const float bfz = -bb[d]      * L2E;
        const float brz = -bb[DD + d] * L2E;
        __half* xh = Xhi + (size_t)b * DD + d;
        __half* xl = Xlo + (size_t)b * DD + d;
        const int odd = ch & 1;
        const int pr = ch >> 1;

        float c = 0.0f;
        for (int k = 0; k < NCH; ++k) {
            barsync(mainbar, 128);
            #pragma unroll
            for (int i = 0; i < CHUNK; ++i) {
                const int t = k * CHUNK + i;
                const int s = t & (RING - 1);
                const float xt = fXT[s * 64 + ch];
                const float fp = fFP[s * 64 + ch];
                const float rp = fRP[s * 64 + ch];
                const uint32_t hu = uXH[s * 32 + pr];
                const uint32_t lu = uXL[s * 32 + pr];

                const float zf = fmaf(vf2, c, fmaf(fp, -L2E, bfz));
                const float f  = rcpf(1.0f + ex2f(zf));
                c = fmaf(f, c - xt, xt);

                const float2 hv = __half22float2(*(const __half2*)&hu);
                const float2 lv = __half22float2(*(const __half2*)&lu);
                const float xo = (odd ? hv.y : hv.x) + (odd ? lv.y : lv.x);
                const float zr = fmaf(vr2, c, fmaf(rp, -L2E, brz));
                const float r  = rcpf(1.0f + ex2f(zr));
                const float h  = fmaf(r, c - xo, xo);

                __half hh, hl;
                f16split(h, hh, hl);
                xh[(size_t)t * xs] = hh;
                xl[(size_t)t * xs] = hl;
            }
            if (k & 1) {   // row-block k>>1 fully written by this unit
                __threadfence();
                barsync(pubbar, 64);
                if (ch == 0) atomicAdd(&g_sprog[k >> 1], 1u);
            }
        }
    }
}

// ---------------------------------------------------------------- mega kernel
__global__ void __launch_bounds__(256, 2)
mega(const __half* __restrict__ Wh,
     float* __restrict__ U,
     __half* __restrict__ Xhi, __half* __restrict__ Xlo,
     const float* __restrict__ sru_v, const float* __restrict__ sru_b,
     const float* __restrict__ fc_b, float* __restrict__ out) {
    extern __shared__ __align__(16) char smem_raw[];
    __shared__ unsigned s_task;

    for (;;) {
        if (threadIdx.x == 0) s_task = atomicAdd(&g_task, 1u);
        __syncthreads();
        const unsigned task = s_task;
        if (task >= NTASKS) return;

        if (task < LAY * TASKS_PER_LAYER) {
            const int L = task / TASKS_PER_LAYER;
            const int r = task % TASKS_PER_LAYER;
            if (r < 768) {
                gemm_tile(Xhi, Wh + (size_t)L * KTOT * NSRU, U, nullptr,
                          NSRU, (r / 24) * 128, (r % 24) * 128,
                          false, smem_raw, 128u * (unsigned)L);
            } else {
                sru_task2(U, Xhi, Xlo,
                          sru_v + (size_t)L * 2 * DD, sru_b + (size_t)L * 2 * DD,
                          r - 768, 24u * (unsigned)(L + 1), smem_raw);
            }
        } else {
            const int fc = task - LAY * TASKS_PER_LAYER;   // 0..127
            gemm_tile(Xhi, Wh + (size_t)LAY * KTOT * NSRU, out, fc_b,
                      NTOK, (fc >> 2) * 128, (fc & 3) * 128,
                      true, smem_raw, 128u * LAY);
        }
        __syncthreads();   // reconverge + protect s_task/smem before next pop
    }
}

// ---------------------------------------------------------------- fused prep
#define CONV_BLKS  4096
#define SPLIT_BLKS 3200
#define PREP_BLKS  (CONV_BLKS + SPLIT_BLKS + 1)

__global__ void __launch_bounds__(1024)
prep_all(const float* __restrict__ feats, const float* __restrict__ w,
         const float* __restrict__ bptr,
         __half* __restrict__ Xhi, __half* __restrict__ Xlo,
         const float* __restrict__ Wsru, const float* __restrict__ Wfc,
         __half* __restrict__ Wh,
         const int* __restrict__ lenbuf, float* outf, long long* outll,
         int rem) {
    __shared__ float s[32][33];
    const int blk = blockIdx.x;
    const int tid = threadIdx.x;

    if (blk < CONV_BLKS) {
        const int tx = tid & 31, ty = tid >> 5;
        const int bx = blk & 15, by = (blk >> 4) & 31, bz = blk >> 9;
        const int t = bx * 32 + tx;
        const int f = by * 32 + ty;
        const int b = bz;

        float acc = bptr[0];
        const float* base = feats + ((size_t)(b * CIN) * FD + f) * TD + t;
        #pragma unroll
        for (int c = 0; c < CIN; ++c)
            acc = fmaf(base[(size_t)c * FD * TD], w[c], acc);
        s[ty][tx] = fmaxf(acc, 0.0f);
        __syncthreads();

        const int t2 = bx * 32 + ty;
        const int f2 = by * 32 + tx;
        const float x = s[tx][ty];
        const size_t o = (size_t)(t2 * BB + b) * DD + f2;
        __half h, l;
        f16split(x, h, l);
        Xhi[o] = h;  Xlo[o] = l;
    } else if (blk < CONV_BLKS + SPLIT_BLKS) {
        const size_t i = (size_t)(blk - CONV_BLKS) * 1024 + tid;
        const size_t n4sru = (size_t)LAY * NSRU * KTOT / 4;
        const float4 x = (i < n4sru) ? ((const float4*)Wsru)[i]
                                     : ((const float4*)Wfc)[i - n4sru];
        __half h[4];
        h[0] = __float2half_rn(x.x);
        h[1] = __float2half_rn(x.y);
        h[2] = __float2half_rn(x.z);
        h[3] = __float2half_rn(x.w);
        ((ulonglong1*)Wh)[i] = *(ulonglong1*)h;
    } else {
        if (tid < 32) { g_prog[tid] = 0u; g_sprog[tid] = 0u; }
        if (tid == 32) g_task = 0u;
        if (tid < BB && rem > 0) {
            const bool in64 = (lenbuf[1] == 0 && lenbuf[3] == 0 &&
                               lenbuf[5] == 0 && lenbuf[7] == 0);
            const long long val = in64 ? (long long)lenbuf[2 * tid]
                                       : (long long)lenbuf[tid];
            const long long hv = val >> 1;
            if (rem >= 16)      outll[tid] = hv;
            else if (rem >= 8)  outf[tid]  = (float)hv;
        }
    }
}

// ---------------------------------------------------------------- host side
extern "C" void kernel_launch(void* const* d_in, const int* in_sizes, int n_in,
                              void* d_out, int out_size) {
    const float* feats  = (const float*)d_in[0];
    const int*   slen   = (const int*)d_in[1];
    const float* conv_w = (const float*)d_in[2];
    const float* conv_b = (const float*)d_in[3];
    const float* sru_W  = (const float*)d_in[4];
    const float* sru_v  = (const float*)d_in[5];
    const float* sru_b  = (const float*)d_in[6];
    const float* fc_w   = (const float*)d_in[7];
    const float* fc_b   = (const float*)d_in[8];

    float* Up;
    __half *Xhi, *Xlo, *Wh;
    cudaGetSymbolAddress((void**)&Xhi, g_Xhi);
    cudaGetSymbolAddress((void**)&Xlo, g_Xlo);
    cudaGetSymbolAddress((void**)&Up,  g_U);
    cudaGetSymbolAddress((void**)&Wh,  g_Wh);

    cudaFuncSetAttribute(mega,
                         cudaFuncAttributeMaxDynamicSharedMemorySize, SMEM_GEMM);

    // prep: conv + weight split + lengths tail + counter reset
    {
        const int rem = out_size - LOGITS_ELEMS;
        float* outf = (float*)d_out + LOGITS_ELEMS;
        long long* outll = (long long*)((char*)d_out + (size_t)LOGITS_ELEMS * 4);
        prep_all<<<PREP_BLKS, 1024>>>(feats, conv_w, conv_b, Xhi, Xlo,
                                      sru_W, fc_w, Wh, slen, outf, outll, rem);
    }

    // whole network: 4x(GEMM+SRU) + FC in one persistent work-queue kernel
    mega<<<MEGA_GRID, 256, SMEM_GEMM>>>(Wh, Up, Xhi, Xlo,
                                        sru_v, sru_b, fc_b, (float*)d_out);
}